// round 1
// baseline (speedup 1.0000x reference)
#include <cuda_runtime.h>
#include <cstdint>

// Problem constants (fixed shapes)
#define PN    100000   // nodes
#define PE    100000   // hyperedges
#define PNNZ  800000   // edges (nnz)
#define PR    4        // ranks
#define PF    64       // features

// Scratch: he_feat[E][F]  (25.6 MB)  -- __device__ global, no allocation
__device__ float g_he_feat[(size_t)PE * PF];
// index dtype flag: 1 if indices are int64, 0 if int32
__device__ int g_is64;

__device__ __forceinline__ long long load_idx(const void* p, long long i, int is64) {
    if (is64) return ((const long long*)p)[i];
    return (long long)((const int*)p)[i];
}

// --- dtype sniff: for int64 little-endian indices < 2^31, every odd 32-bit word is 0.
__global__ void detect_idx_dtype(const void* rows) {
    if (blockIdx.x == 0 && threadIdx.x == 0) {
        const int* p = (const int*)rows;
        int all0 = 1;
        #pragma unroll 4
        for (int i = 0; i < 1024; i++) {
            if (p[2 * i + 1] != 0) { all0 = 0; break; }
        }
        g_is64 = all0;
    }
}

// --- zero he_feat scratch (must happen every replay)
__global__ void zero_he_feat() {
    long long t = (long long)blockIdx.x * blockDim.x + threadIdx.x;
    long long total = (long long)PE * PF;
    for (; t < total; t += (long long)gridDim.x * blockDim.x)
        g_he_feat[t] = 0.0f;
}

// --- init output: rank 3 gets x, ranks 0..2 get 0
__global__ void init_out(float* __restrict__ out, const float* __restrict__ x) {
    long long t = (long long)blockIdx.x * blockDim.x + threadIdx.x;
    long long total = (long long)PN * PR * PF;
    for (; t < total; t += (long long)gridDim.x * blockDim.x) {
        int inner = (int)(t & (PR * PF - 1));       // 0..255
        if (inner >= (PR - 1) * PF) {
            long long n = t >> 8;                    // /256
            out[t] = x[n * PF + (inner - (PR - 1) * PF)];
        } else {
            out[t] = 0.0f;
        }
    }
}

// --- pass 1: he_feat[cols[i]] += x[rows[i]] * vals[i]   (warp per edge)
__global__ void scatter_edge_feat(const float* __restrict__ x,
                                  const float* __restrict__ vals,
                                  const void* __restrict__ rows,
                                  const void* __restrict__ cols) {
    int is64 = g_is64;
    long long gw = ((long long)blockIdx.x * blockDim.x + threadIdx.x) >> 5;
    int lane = threadIdx.x & 31;
    if (gw >= PNNZ) return;
    long long row = load_idx(rows, gw, is64);
    long long col = load_idx(cols, gw, is64);
    float v = vals[gw];
    const float* xr = x + row * PF;
    float a0 = xr[lane] * v;
    float a1 = xr[lane + 32] * v;
    float* hf = g_he_feat + col * PF;
    atomicAdd(hf + lane, a0);
    atomicAdd(hf + lane + 32, a1);
}

// --- pass 2: out[rows[i], r, :] += rank_masks[r, he_idxs[cols[i]]] * vals[i] * he_feat[cols[i], :]
//     only r = 0..2 (r=3 is overwritten by x)
__global__ void scatter_node_feat(float* __restrict__ out,
                                  const float* __restrict__ rank_masks,
                                  const float* __restrict__ vals,
                                  const void* __restrict__ he_idxs,
                                  const void* __restrict__ rows,
                                  const void* __restrict__ cols) {
    int is64 = g_is64;
    long long gw = ((long long)blockIdx.x * blockDim.x + threadIdx.x) >> 5;
    int lane = threadIdx.x & 31;
    if (gw >= PNNZ) return;
    long long row = load_idx(rows, gw, is64);
    long long col = load_idx(cols, gw, is64);
    float v = vals[gw];
    long long he = load_idx(he_idxs, col, is64);

    float s0 = rank_masks[(size_t)0 * PE + he] * v;
    float s1 = rank_masks[(size_t)1 * PE + he] * v;
    float s2 = rank_masks[(size_t)2 * PE + he] * v;

    const float* hf = g_he_feat + col * PF;
    float h0 = hf[lane];
    float h1 = hf[lane + 32];

    float* o = out + row * (PR * PF);
    atomicAdd(o + 0 * PF + lane,      s0 * h0);
    atomicAdd(o + 0 * PF + lane + 32, s0 * h1);
    atomicAdd(o + 1 * PF + lane,      s1 * h0);
    atomicAdd(o + 1 * PF + lane + 32, s1 * h1);
    atomicAdd(o + 2 * PF + lane,      s2 * h0);
    atomicAdd(o + 2 * PF + lane + 32, s2 * h1);
}

extern "C" void kernel_launch(void* const* d_in, const int* in_sizes, int n_in,
                              void* d_out, int out_size) {
    const float* x          = (const float*)d_in[0];   // (N, F)
    const float* rank_masks = (const float*)d_in[1];   // (R, E)
    const float* vals       = (const float*)d_in[2];   // (NNZ,)
    const void*  he_idxs    = d_in[3];                 // (E,)   int32 or int64
    const void*  rows       = d_in[4];                 // (NNZ,)
    const void*  cols       = d_in[5];                 // (NNZ,)
    float* out = (float*)d_out;                        // (N, R, F)

    detect_idx_dtype<<<1, 32>>>(rows);

    {
        long long total = (long long)PE * PF;
        int blocks = (int)((total + 255) / 256);
        if (blocks > 8192) blocks = 8192;
        zero_he_feat<<<blocks, 256>>>();
    }
    {
        long long total = (long long)PN * PR * PF;
        int blocks = (int)((total + 255) / 256);
        if (blocks > 16384) blocks = 16384;
        init_out<<<blocks, 256>>>(out, x);
    }
    {
        long long threads = (long long)PNNZ * 32;
        int blocks = (int)((threads + 255) / 256);
        scatter_edge_feat<<<blocks, 256>>>(x, vals, rows, cols);
    }
    {
        long long threads = (long long)PNNZ * 32;
        int blocks = (int)((threads + 255) / 256);
        scatter_node_feat<<<blocks, 256>>>(out, rank_masks, vals, he_idxs, rows, cols);
    }
}

// round 2
// speedup vs baseline: 1.2023x; 1.2023x over previous
#include <cuda_runtime.h>
#include <cstdint>

// Problem constants (fixed shapes)
#define PN    100000   // nodes
#define PE    100000   // hyperedges
#define PNNZ  800000   // edges (nnz)
#define PR    4        // ranks
#define PF    64       // features

// Scratch: he_feat[E][F]  (25.6 MB)  -- __device__ global, no allocation
__device__ __align__(16) float g_he_feat[(size_t)PE * PF];
// index dtype flag: 1 if indices are int64, 0 if int32
__device__ int g_is64;

__device__ __forceinline__ long long load_idx(const void* p, long long i, int is64) {
    if (is64) return ((const long long*)p)[i];
    return (long long)((const int*)p)[i];
}

// Vectorized global reduction: one instruction commits 16B (sm_90+)
__device__ __forceinline__ void red_add_v4(float* addr, float a, float b, float c, float d) {
    asm volatile("red.global.add.v4.f32 [%0], {%1, %2, %3, %4};"
                 :: "l"(addr), "f"(a), "f"(b), "f"(c), "f"(d) : "memory");
}

// --- dtype sniff: for int64 little-endian indices < 2^31, every odd 32-bit word is 0.
__global__ void detect_idx_dtype(const void* rows) {
    if (blockIdx.x == 0 && threadIdx.x == 0) {
        const int* p = (const int*)rows;
        int all0 = 1;
        #pragma unroll 4
        for (int i = 0; i < 1024; i++) {
            if (p[2 * i + 1] != 0) { all0 = 0; break; }
        }
        g_is64 = all0;
    }
}

// --- zero he_feat scratch (must happen every replay), vectorized
__global__ void zero_he_feat() {
    long long t = (long long)blockIdx.x * blockDim.x + threadIdx.x;
    long long total = (long long)PE * PF / 4;
    float4* p = (float4*)g_he_feat;
    float4 z = make_float4(0.f, 0.f, 0.f, 0.f);
    for (; t < total; t += (long long)gridDim.x * blockDim.x)
        p[t] = z;
}

// --- init output: rank 3 gets x, ranks 0..2 get 0 (vectorized float4)
__global__ void init_out(float4* __restrict__ out, const float4* __restrict__ x) {
    long long t = (long long)blockIdx.x * blockDim.x + threadIdx.x;
    long long total = (long long)PN * PR * PF / 4;   // vec4 count; 64 per node
    for (; t < total; t += (long long)gridDim.x * blockDim.x) {
        int inner = (int)(t & 63);                    // vec4 within node row
        if (inner >= 48) {                            // rank 3 region
            long long n = t >> 6;
            out[t] = x[n * 16 + (inner - 48)];
        } else {
            out[t] = make_float4(0.f, 0.f, 0.f, 0.f);
        }
    }
}

// --- pass 1: he_feat[cols[i]] += x[rows[i]] * vals[i]
//     16 threads per edge, each handles one float4 (64 floats total).
__global__ void scatter_edge_feat(const float4* __restrict__ x,
                                  const float* __restrict__ vals,
                                  const void* __restrict__ rows,
                                  const void* __restrict__ cols) {
    int is64 = g_is64;
    long long gt = (long long)blockIdx.x * blockDim.x + threadIdx.x;
    long long e = gt >> 4;
    int sub = threadIdx.x & 15;
    if (e >= PNNZ) return;
    long long row = load_idx(rows, e, is64);
    long long col = load_idx(cols, e, is64);
    float v = vals[e];
    float4 a = x[row * 16 + sub];
    float* hf = g_he_feat + col * PF + sub * 4;
    red_add_v4(hf, a.x * v, a.y * v, a.z * v, a.w * v);
}

// --- pass 2: out[rows[i], r, :] += rank_masks[r, he_idxs[cols[i]]] * vals[i] * he_feat[cols[i], :]
//     only r = 0..2 (r=3 overwritten by x). Warp per edge.
//     48 vec4 outputs per edge: lane k handles vec4 k (r = k/16), lanes 0..15 also handle vec4 32+k (r=2).
__global__ void scatter_node_feat(float* __restrict__ out,
                                  const float* __restrict__ rank_masks,
                                  const float* __restrict__ vals,
                                  const void* __restrict__ he_idxs,
                                  const void* __restrict__ rows,
                                  const void* __restrict__ cols) {
    int is64 = g_is64;
    long long gw = ((long long)blockIdx.x * blockDim.x + threadIdx.x) >> 5;
    int lane = threadIdx.x & 31;
    if (gw >= PNNZ) return;
    long long row = load_idx(rows, gw, is64);
    long long col = load_idx(cols, gw, is64);
    float v = vals[gw];
    long long he = load_idx(he_idxs, col, is64);

    float s0 = rank_masks[(size_t)0 * PE + he] * v;
    float s1 = rank_masks[(size_t)1 * PE + he] * v;
    float s2 = rank_masks[(size_t)2 * PE + he] * v;

    const float4* hf4 = (const float4*)(g_he_feat + col * PF);
    int f4 = lane & 15;
    float4 h = hf4[f4];

    float* o = out + row * (PR * PF);

    // first 32 vec4s: ranks 0 and 1
    float sA = (lane < 16) ? s0 : s1;
    red_add_v4(o + lane * 4, h.x * sA, h.y * sA, h.z * sA, h.w * sA);

    // vec4s 32..47: rank 2 (lanes 0..15)
    if (lane < 16) {
        red_add_v4(o + (32 + lane) * 4, h.x * s2, h.y * s2, h.z * s2, h.w * s2);
    }
}

extern "C" void kernel_launch(void* const* d_in, const int* in_sizes, int n_in,
                              void* d_out, int out_size) {
    const float* x          = (const float*)d_in[0];   // (N, F)
    const float* rank_masks = (const float*)d_in[1];   // (R, E)
    const float* vals       = (const float*)d_in[2];   // (NNZ,)
    const void*  he_idxs    = d_in[3];                 // (E,)   int32 or int64
    const void*  rows       = d_in[4];                 // (NNZ,)
    const void*  cols       = d_in[5];                 // (NNZ,)
    float* out = (float*)d_out;                        // (N, R, F)

    detect_idx_dtype<<<1, 32>>>(rows);

    {
        long long total = (long long)PE * PF / 4;
        int blocks = (int)((total + 255) / 256);
        if (blocks > 4096) blocks = 4096;
        zero_he_feat<<<blocks, 256>>>();
    }
    {
        long long total = (long long)PN * PR * PF / 4;
        int blocks = (int)((total + 255) / 256);
        if (blocks > 8192) blocks = 8192;
        init_out<<<blocks, 256>>>((float4*)out, (const float4*)x);
    }
    {
        long long threads = (long long)PNNZ * 16;
        int blocks = (int)((threads + 255) / 256);
        scatter_edge_feat<<<blocks, 256>>>((const float4*)x, vals, rows, cols);
    }
    {
        long long threads = (long long)PNNZ * 32;
        int blocks = (int)((threads + 255) / 256);
        scatter_node_feat<<<blocks, 256>>>(out, rank_masks, vals, he_idxs, rows, cols);
    }
}